// round 1
// baseline (speedup 1.0000x reference)
#include <cuda_runtime.h>

#define NB 8
#define NE 16
#define NC 32
#define NPIX (512*512)
#define PPW 2048
#define WPB 4
#define BPB (NPIX/(PPW*WPB))   /* 32 blocks per batch */

// Scratch (no allocations allowed) — tiny, stays in L2.
__device__ float g_sums[NB*NC*NE];          // [b][c][e]
__device__ float g_counts[NB*NC];           // [b][c]
__device__ float g_var[NB*NC];              // [b][c]
__device__ float g_centers[NB*NE*(NC+1)];   // [b][e][c], slot c=0 == zeros (bg)

__device__ __forceinline__ unsigned f2tf(float x){
    unsigned r; asm("cvt.rna.tf32.f32 %0, %1;" : "=r"(r) : "f"(x)); return r;
}

__device__ __forceinline__ void mma8(float* d,
    unsigned a0, unsigned a1, unsigned a2, unsigned a3,
    unsigned b0, unsigned b1){
    asm volatile("mma.sync.aligned.m16n8k8.row.col.f32.tf32.tf32.f32 "
        "{%0,%1,%2,%3}, {%4,%5,%6,%7}, {%8,%9}, {%0,%1,%2,%3};"
        : "+f"(d[0]), "+f"(d[1]), "+f"(d[2]), "+f"(d[3])
        : "r"(a0), "r"(a1), "r"(a2), "r"(a3), "r"(b0), "r"(b1));
}

__device__ __forceinline__ float sqrt_fast(float x){
    float r; asm("sqrt.approx.f32 %0, %1;" : "=f"(r) : "f"(x)); return r;
}

// ---------------- K0: zero scratch ----------------
__global__ void k_zero(){
    int i = blockIdx.x * blockDim.x + threadIdx.x;
    if (i < NB*NC*NE)      g_sums[i]    = 0.f;
    if (i < NB*NC)         { g_counts[i] = 0.f; g_var[i] = 0.f; }
    if (i < NB*NE*(NC+1))  g_centers[i] = 0.f;
}

// ---------------- K1: segment sums + counts via onehot-MMA ----------------
__global__ void __launch_bounds__(128) k_sums(const float* __restrict__ emb,
                                              const int*   __restrict__ mask){
    int b    = blockIdx.x / BPB;
    int blk  = blockIdx.x % BPB;
    int warp = threadIdx.x >> 5;
    int lane = threadIdx.x & 31;
    int t    = lane & 3;       // threadID_in_group (k index)
    int g    = lane >> 2;      // groupID (row / col group)

    const float* eb = emb + (size_t)b * NE * NPIX;
    const int*   mb = mask + (size_t)b * NPIX;
    const float* r0 = eb + (size_t)g       * NPIX;   // channel g
    const float* r1 = eb + (size_t)(g + 8) * NPIX;   // channel g+8
    int p0 = (blk * WPB + warp) * PPW;

    float d[2][2][4];
    #pragma unroll
    for (int mi=0; mi<2; mi++)
        #pragma unroll
        for (int ni=0; ni<2; ni++)
            #pragma unroll
            for (int j=0; j<4; j++) d[mi][ni][j] = 0.f;
    int cnt[4] = {0,0,0,0};

    const unsigned ONE = 0x3F800000u;

    for (int i = 0; i < PPW; i += 32){
        int lab32 = mb[p0 + i + lane];
        #pragma unroll
        for (int q = 0; q < 4; q++){
            int pix  = p0 + i + q*8;
            int labT  = __shfl_sync(0xffffffffu, lab32, q*8 + t);
            int labT4 = __shfl_sync(0xffffffffu, lab32, q*8 + t + 4);

            unsigned b00 = f2tf(r0[pix + t]);
            unsigned b01 = f2tf(r0[pix + t + 4]);
            unsigned b10 = f2tf(r1[pix + t]);
            unsigned b11 = f2tf(r1[pix + t + 4]);

            // one-hot A fragments: row r <-> label r+1
            bool p00 = (labT  == g + 1),  p01 = (labT  == g + 9);
            bool p02 = (labT4 == g + 1),  p03 = (labT4 == g + 9);
            bool p10 = (labT  == g + 17), p11 = (labT  == g + 25);
            bool p12 = (labT4 == g + 17), p13 = (labT4 == g + 25);
            unsigned a00 = p00 ? ONE : 0u, a01 = p01 ? ONE : 0u;
            unsigned a02 = p02 ? ONE : 0u, a03 = p03 ? ONE : 0u;
            unsigned a10 = p10 ? ONE : 0u, a11 = p11 ? ONE : 0u;
            unsigned a12 = p12 ? ONE : 0u, a13 = p13 ? ONE : 0u;

            mma8(d[0][0], a00,a01,a02,a03, b00,b01);
            mma8(d[0][1], a00,a01,a02,a03, b10,b11);
            mma8(d[1][0], a10,a11,a12,a13, b00,b01);
            mma8(d[1][1], a10,a11,a12,a13, b10,b11);

            cnt[0] += (int)p00 + (int)p02;   // label g+1
            cnt[1] += (int)p01 + (int)p03;   // label g+9
            cnt[2] += (int)p10 + (int)p12;   // label g+17
            cnt[3] += (int)p11 + (int)p13;   // label g+25
        }
    }

    // counts: reduce over t within each quad (lanes g*4 .. g*4+3)
    #pragma unroll
    for (int j=0; j<4; j++){
        cnt[j] += __shfl_xor_sync(0xffffffffu, cnt[j], 1);
        cnt[j] += __shfl_xor_sync(0xffffffffu, cnt[j], 2);
    }
    if (t == 0){
        atomicAdd(&g_counts[b*NC + g     ], (float)cnt[0]);
        atomicAdd(&g_counts[b*NC + g + 8 ], (float)cnt[1]);
        atomicAdd(&g_counts[b*NC + g + 16], (float)cnt[2]);
        atomicAdd(&g_counts[b*NC + g + 24], (float)cnt[3]);
    }
    #pragma unroll
    for (int mi=0; mi<2; mi++)
        #pragma unroll
        for (int ni=0; ni<2; ni++)
            #pragma unroll
            for (int j=0; j<4; j++){
                int c = g + ((j >> 1) & 1) * 8 + mi * 16;
                int e = 2*t + (j & 1) + ni * 8;
                atomicAdd(&g_sums[(b*NC + c)*NE + e], d[mi][ni][j]);
            }
}

// ---------------- K2: centers = sums / max(counts,1) ----------------
__global__ void k_centers(){
    int i = blockIdx.x * blockDim.x + threadIdx.x;
    if (i >= NB*NC*NE) return;
    int e = i & 15, c = (i >> 4) & 31, b = i >> 9;
    float cnt = g_counts[b*NC + c];
    float ctr = g_sums[i] / fmaxf(cnt, 1.f);
    g_centers[(b*NE + e)*(NC+1) + (c + 1)] = ctr;
}

// ---------------- K3: variance term via onehot-MMA ----------------
__global__ void __launch_bounds__(128) k_var(const float* __restrict__ emb,
                                             const int*   __restrict__ mask){
    __shared__ float scent[NE*(NC+1)];
    int b    = blockIdx.x / BPB;
    int blk  = blockIdx.x % BPB;
    int warp = threadIdx.x >> 5;
    int lane = threadIdx.x & 31;
    int t    = lane & 3;
    int g    = lane >> 2;

    for (int idx = threadIdx.x; idx < NE*(NC+1); idx += 128)
        scent[idx] = g_centers[b*NE*(NC+1) + idx];
    __syncthreads();

    const float* eb = emb + (size_t)b * NE * NPIX;
    const int*   mb = mask + (size_t)b * NPIX;
    const float* r0 = eb + (size_t)g       * NPIX;
    const float* r1 = eb + (size_t)(g + 8) * NPIX;
    int p0 = (blk * WPB + warp) * PPW;

    float dv0[4] = {0,0,0,0};
    float dv1[4] = {0,0,0,0};
    const unsigned ONE = 0x3F800000u;

    for (int i = 0; i < PPW; i += 32){
        int lab32 = mb[p0 + i + lane];
        #pragma unroll
        for (int q = 0; q < 4; q++){
            int pix  = p0 + i + q*8;
            int labT  = __shfl_sync(0xffffffffu, lab32, q*8 + t);
            int labT4 = __shfl_sync(0xffffffffu, lab32, q*8 + t + 4);

            float v00 = r0[pix + t],     v01 = r0[pix + t + 4];
            float v10 = r1[pix + t],     v11 = r1[pix + t + 4];
            float c00 = scent[g*(NC+1)       + labT ];
            float c01 = scent[g*(NC+1)       + labT4];
            float c10 = scent[(g+8)*(NC+1)   + labT ];
            float c11 = scent[(g+8)*(NC+1)   + labT4];
            float e00 = v00 - c00, e01 = v01 - c01;
            float e10 = v10 - c10, e11 = v11 - c11;
            float pT  = e00*e00 + e10*e10;     // channels g, g+8 for pixel t
            float pT4 = e01*e01 + e11*e11;     // for pixel t+4
            // reduce across the 8 g-lanes sharing the same t
            pT  += __shfl_xor_sync(0xffffffffu, pT , 4);
            pT  += __shfl_xor_sync(0xffffffffu, pT , 8);
            pT  += __shfl_xor_sync(0xffffffffu, pT , 16);
            pT4 += __shfl_xor_sync(0xffffffffu, pT4, 4);
            pT4 += __shfl_xor_sync(0xffffffffu, pT4, 8);
            pT4 += __shfl_xor_sync(0xffffffffu, pT4, 16);

            float h  = sqrt_fast(pT ) - 0.5f;  h  = fmaxf(h , 0.f); h  *= h;
            float h4 = sqrt_fast(pT4) - 0.5f;  h4 = fmaxf(h4, 0.f); h4 *= h4;

            unsigned bh0 = (g == 0) ? f2tf(h ) : 0u;   // B[k=t  ][n=0]
            unsigned bh1 = (g == 0) ? f2tf(h4) : 0u;   // B[k=t+4][n=0]

            unsigned a00 = (labT  == g + 1 ) ? ONE : 0u;
            unsigned a01 = (labT  == g + 9 ) ? ONE : 0u;
            unsigned a02 = (labT4 == g + 1 ) ? ONE : 0u;
            unsigned a03 = (labT4 == g + 9 ) ? ONE : 0u;
            unsigned a10 = (labT  == g + 17) ? ONE : 0u;
            unsigned a11 = (labT  == g + 25) ? ONE : 0u;
            unsigned a12 = (labT4 == g + 17) ? ONE : 0u;
            unsigned a13 = (labT4 == g + 25) ? ONE : 0u;

            mma8(dv0, a00,a01,a02,a03, bh0,bh1);
            mma8(dv1, a10,a11,a12,a13, bh0,bh1);
        }
    }
    // useful outputs: col 0 -> lanes with t==0, elements c0 (row g) and c2 (row g+8)
    if (t == 0){
        atomicAdd(&g_var[b*NC + g     ], dv0[0]);
        atomicAdd(&g_var[b*NC + g + 8 ], dv0[2]);
        atomicAdd(&g_var[b*NC + g + 16], dv1[0]);
        atomicAdd(&g_var[b*NC + g + 24], dv1[2]);
    }
}

// ---------------- K4: finalize ----------------
__global__ void __launch_bounds__(256) k_final(float* __restrict__ out){
    __shared__ float centers_s[NB*NC*NE];   // 16 KB
    __shared__ float s_var[NB], s_dist[NB], s_reg[NB], s_np[NB], s_npairs[NB];
    int tid = threadIdx.x;

    for (int i = tid; i < NB*NC*NE; i += 256){
        int c = (i >> 4) & 31, b = i >> 9;
        centers_s[i] = g_sums[i] / fmaxf(g_counts[b*NC + c], 1.f);
    }
    if (tid < NB){ s_var[tid]=0.f; s_dist[tid]=0.f; s_reg[tid]=0.f; s_np[tid]=0.f; s_npairs[tid]=0.f; }
    __syncthreads();

    // per-(b,c): variance + reg + presence
    for (int i = tid; i < NB*NC; i += 256){
        int b = i >> 5, c = i & 31;
        float cnt = g_counts[i];
        if (cnt > 0.f){
            atomicAdd(&s_np[b], 1.f);
            atomicAdd(&s_var[b], g_var[i] / cnt);
            float ss = 0.f;
            #pragma unroll
            for (int e = 0; e < NE; e++){
                float x = centers_s[(b*NC + c)*NE + e];
                ss += x * x;
            }
            atomicAdd(&s_reg[b], sqrtf(ss));
        }
    }
    // pairwise distance term: 496 pairs per batch
    for (int p = tid; p < NB*496; p += 256){
        int b = p / 496, pr = p % 496;
        int i0 = 0, rem = pr;
        while (rem >= (NC - 1 - i0)){ rem -= (NC - 1 - i0); i0++; }
        int j0 = i0 + 1 + rem;
        if (g_counts[b*NC + i0] > 0.f && g_counts[b*NC + j0] > 0.f){
            float ss = 0.f;
            #pragma unroll
            for (int e = 0; e < NE; e++){
                float dd = centers_s[(b*NC + i0)*NE + e] - centers_s[(b*NC + j0)*NE + e];
                ss += dd * dd;
            }
            float ph = fmaxf(3.0f - sqrtf(ss), 0.f);   // 2*DELTA_DIST = 3
            ph *= ph;
            atomicAdd(&s_dist[b], ph);
            atomicAdd(&s_npairs[b], 1.f);
        }
    }
    __syncthreads();

    if (tid == 0){
        float lv = 0.f, ld = 0.f, lr = 0.f, vb = 0.f;
        for (int b = 0; b < NB; b++){
            float np = s_np[b];
            if (np > 0.f){
                vb += 1.f;
                lv += s_var[b] / np;
                lr += s_reg[b] / np;
                ld += (s_npairs[b] > 0.f) ? (s_dist[b] / s_npairs[b]) : 0.f;
            }
        }
        float denom  = fmaxf(vb, 1.f);
        float L_var  = (vb > 0.f) ? lv / denom : 0.f;
        float L_dist = (vb > 0.f) ? ld / denom : 0.f;
        float L_reg  = (vb > 0.f) ? lr / denom : 0.f;
        float total  = 1.0f * L_var + 1.0f * L_dist + 0.001f * L_reg;
        out[0] = total;
        out[1] = L_var;
        out[2] = L_dist;
        out[3] = L_reg;
    }
}

extern "C" void kernel_launch(void* const* d_in, const int* in_sizes, int n_in,
                              void* d_out, int out_size){
    (void)in_sizes; (void)n_in; (void)out_size;
    const float* emb  = (const float*)d_in[0];
    const int*   mask = (const int*)d_in[1];
    k_zero   <<<17, 256>>>();
    k_sums   <<<NB*BPB, 128>>>(emb, mask);
    k_centers<<<16, 256>>>();
    k_var    <<<NB*BPB, 128>>>(emb, mask);
    k_final  <<<1, 256>>>((float*)d_out);
}

// round 2
// speedup vs baseline: 1.7225x; 1.7225x over previous
#include <cuda_runtime.h>

#define NB 8
#define NE 16
#define NC 32
#define NPIX (512*512)

// k_sums config
#define PPW 512
#define WPB 4
#define BPB (NPIX/(PPW*WPB))     /* 128 blocks per batch -> grid 1024 */

// k_var config
#define VPT 4                    /* pixels per thread (one float4) */
#define VBL 256                  /* threads per block */
#define VBPB (NPIX/(VBL*VPT))    /* 256 blocks per batch -> grid 2048 */

// Scratch (no allocations allowed) — tiny, stays in L2.
__device__ float g_sums[NB*NC*NE];          // [b][c][e]
__device__ float g_counts[NB*NC];           // [b][c]
__device__ float g_var[NB*NC];              // [b][c]
__device__ float g_centers[NB*NE*(NC+1)];   // [b][e][c], slot c=0 == zeros (bg)

__device__ __forceinline__ unsigned f2tf(float x){
    unsigned r; asm("cvt.rna.tf32.f32 %0, %1;" : "=r"(r) : "f"(x)); return r;
}

__device__ __forceinline__ void mma8(float* d,
    unsigned a0, unsigned a1, unsigned a2, unsigned a3,
    unsigned b0, unsigned b1){
    asm volatile("mma.sync.aligned.m16n8k8.row.col.f32.tf32.tf32.f32 "
        "{%0,%1,%2,%3}, {%4,%5,%6,%7}, {%8,%9}, {%0,%1,%2,%3};"
        : "+f"(d[0]), "+f"(d[1]), "+f"(d[2]), "+f"(d[3])
        : "r"(a0), "r"(a1), "r"(a2), "r"(a3), "r"(b0), "r"(b1));
}

__device__ __forceinline__ float sqrt_fast(float x){
    float r; asm("sqrt.approx.f32 %0, %1;" : "=f"(r) : "f"(x)); return r;
}

// ---------------- K0: zero scratch ----------------
__global__ void k_zero(){
    int i = blockIdx.x * blockDim.x + threadIdx.x;
    if (i < NB*NC*NE)      g_sums[i]    = 0.f;
    if (i < NB*NC)         { g_counts[i] = 0.f; g_var[i] = 0.f; }
    if (i < NB*NE*(NC+1))  g_centers[i] = 0.f;
}

// ---------------- K1: segment sums + counts via onehot-MMA ----------------
__global__ void __launch_bounds__(128) k_sums(const float* __restrict__ emb,
                                              const int*   __restrict__ mask){
    int b    = blockIdx.x / BPB;
    int blk  = blockIdx.x % BPB;
    int warp = threadIdx.x >> 5;
    int lane = threadIdx.x & 31;
    int t    = lane & 3;       // threadID_in_group (k index)
    int g    = lane >> 2;      // groupID

    const float* eb = emb + (size_t)b * NE * NPIX;
    const int*   mb = mask + (size_t)b * NPIX;
    const float* r0 = eb + (size_t)g       * NPIX;   // channel g
    const float* r1 = eb + (size_t)(g + 8) * NPIX;   // channel g+8
    int p0 = (blk * WPB + warp) * PPW;

    float d[2][2][4];
    #pragma unroll
    for (int mi=0; mi<2; mi++)
        #pragma unroll
        for (int ni=0; ni<2; ni++)
            #pragma unroll
            for (int j=0; j<4; j++) d[mi][ni][j] = 0.f;
    unsigned cnt[4] = {0,0,0,0};
    const unsigned ONE = 0x3F800000u;

    for (int i = 0; i < PPW; i += 32){
        int pix = p0 + i;
        int lab = mb[pix + lane];
        unsigned oh = lab ? (1u << (lab - 1)) : 0u;   // one-hot of this lane's pixel label

        float4 f0a = *(const float4*)(r0 + pix + 4*t);        // ch g,   pixels 4t..4t+3
        float4 f0b = *(const float4*)(r0 + pix + 16 + 4*t);   // ch g,   pixels 16+4t..
        float4 f1a = *(const float4*)(r1 + pix + 4*t);        // ch g+8
        float4 f1b = *(const float4*)(r1 + pix + 16 + 4*t);
        float q0a[4] = {f0a.x, f0a.y, f0a.z, f0a.w};
        float q0b[4] = {f0b.x, f0b.y, f0b.z, f0b.w};
        float q1a[4] = {f1a.x, f1a.y, f1a.z, f1a.w};
        float q1b[4] = {f1b.x, f1b.y, f1b.z, f1b.w};

        #pragma unroll
        for (int j = 0; j < 4; j++){
            // sub-mma j: k=t <-> pixel 4t+j ; k=t+4 <-> pixel 16+4t+j
            unsigned ohA = __shfl_sync(0xffffffffu, oh, 4*t + j);
            unsigned ohB = __shfl_sync(0xffffffffu, oh, 16 + 4*t + j);

            unsigned bA0 = (ohA >> g)      & 1u;  // row g      (class g+1),  k=t
            unsigned bA1 = (ohA >> (g+8))  & 1u;  // row g+8    (class g+9),  k=t
            unsigned bB0 = (ohB >> g)      & 1u;  // row g,      k=t+4
            unsigned bB1 = (ohB >> (g+8))  & 1u;  // row g+8,    k=t+4
            unsigned bA2 = (ohA >> (g+16)) & 1u;
            unsigned bA3 = (ohA >> (g+24)) & 1u;
            unsigned bB2 = (ohB >> (g+16)) & 1u;
            unsigned bB3 = (ohB >> (g+24)) & 1u;

            cnt[0] += bA0 + bB0;
            cnt[1] += bA1 + bB1;
            cnt[2] += bA2 + bB2;
            cnt[3] += bA3 + bB3;

            unsigned a0 = bA0*ONE, a1 = bA1*ONE, a2 = bB0*ONE, a3 = bB1*ONE;
            unsigned a4 = bA2*ONE, a5 = bA3*ONE, a6 = bB2*ONE, a7 = bB3*ONE;

            unsigned b00 = f2tf(q0a[j]);
            unsigned b01 = f2tf(q0b[j]);
            unsigned b10 = f2tf(q1a[j]);
            unsigned b11 = f2tf(q1b[j]);

            mma8(d[0][0], a0,a1,a2,a3, b00,b01);
            mma8(d[0][1], a0,a1,a2,a3, b10,b11);
            mma8(d[1][0], a4,a5,a6,a7, b00,b01);
            mma8(d[1][1], a4,a5,a6,a7, b10,b11);
        }
    }

    // counts: reduce over the 4 t-lanes of each quad
    #pragma unroll
    for (int j=0; j<4; j++){
        cnt[j] += __shfl_xor_sync(0xffffffffu, cnt[j], 1);
        cnt[j] += __shfl_xor_sync(0xffffffffu, cnt[j], 2);
    }
    if (t == 0){
        atomicAdd(&g_counts[b*NC + g     ], (float)cnt[0]);
        atomicAdd(&g_counts[b*NC + g + 8 ], (float)cnt[1]);
        atomicAdd(&g_counts[b*NC + g + 16], (float)cnt[2]);
        atomicAdd(&g_counts[b*NC + g + 24], (float)cnt[3]);
    }
    #pragma unroll
    for (int mi=0; mi<2; mi++)
        #pragma unroll
        for (int ni=0; ni<2; ni++)
            #pragma unroll
            for (int j=0; j<4; j++){
                int c = g + ((j >> 1) & 1) * 8 + mi * 16;
                int e = 2*t + (j & 1) + ni * 8;
                atomicAdd(&g_sums[(b*NC + c)*NE + e], d[mi][ni][j]);
            }
}

// ---------------- K2: centers = sums / max(counts,1) ----------------
__global__ void k_centers(){
    int i = blockIdx.x * blockDim.x + threadIdx.x;
    if (i >= NB*NC*NE) return;
    int e = i & 15, c = (i >> 4) & 31, b = i >> 9;
    float cnt = g_counts[b*NC + c];
    float ctr = g_sums[i] / fmaxf(cnt, 1.f);
    g_centers[(b*NE + e)*(NC+1) + (c + 1)] = ctr;
}

// ---------------- K3: variance term, per-thread pixels ----------------
__global__ void __launch_bounds__(VBL) k_var(const float* __restrict__ emb,
                                             const int*   __restrict__ mask){
    __shared__ float scent[NE*(NC+1)];   // [e][lab], row stride 33 (conflict-friendly)
    __shared__ float svar[NC+1];
    int tid = threadIdx.x;
    int b   = blockIdx.x / VBPB;
    int blk = blockIdx.x % VBPB;

    if (tid < NC+1) svar[tid] = 0.f;
    for (int i = tid; i < NE*(NC+1); i += VBL)
        scent[i] = g_centers[b*NE*(NC+1) + i];
    __syncthreads();

    const float* eb = emb + (size_t)b * NE * NPIX;
    int p0 = (blk * VBL + tid) * VPT;

    int4 lab4 = *(const int4*)(mask + (size_t)b * NPIX + p0);
    int l0 = lab4.x, l1 = lab4.y, l2 = lab4.z, l3 = lab4.w;

    float ss0 = 0.f, ss1 = 0.f, ss2 = 0.f, ss3 = 0.f;
    #pragma unroll
    for (int e = 0; e < NE; e++){
        float4 v = *(const float4*)(eb + (size_t)e * NPIX + p0);
        const float* ce = scent + e*(NC+1);
        float d0 = v.x - ce[l0];  ss0 += d0*d0;
        float d1 = v.y - ce[l1];  ss1 += d1*d1;
        float d2 = v.z - ce[l2];  ss2 += d2*d2;
        float d3 = v.w - ce[l3];  ss3 += d3*d3;
    }

    float h0 = fmaxf(sqrt_fast(ss0) - 0.5f, 0.f); h0 *= h0;
    float h1 = fmaxf(sqrt_fast(ss1) - 0.5f, 0.f); h1 *= h1;
    float h2 = fmaxf(sqrt_fast(ss2) - 0.5f, 0.f); h2 *= h2;
    float h3 = fmaxf(sqrt_fast(ss3) - 0.5f, 0.f); h3 *= h3;

    if (l0) atomicAdd(&svar[l0], h0);
    if (l1) atomicAdd(&svar[l1], h1);
    if (l2) atomicAdd(&svar[l2], h2);
    if (l3) atomicAdd(&svar[l3], h3);
    __syncthreads();

    if (tid >= 1 && tid <= NC){
        float v = svar[tid];
        if (v != 0.f) atomicAdd(&g_var[b*NC + tid - 1], v);
    }
}

// ---------------- K4: finalize ----------------
__global__ void __launch_bounds__(256) k_final(float* __restrict__ out){
    __shared__ float centers_s[NB*NC*NE];   // 16 KB
    __shared__ float s_var[NB], s_dist[NB], s_reg[NB], s_np[NB], s_npairs[NB];
    int tid = threadIdx.x;

    for (int i = tid; i < NB*NC*NE; i += 256){
        int c = (i >> 4) & 31, b = i >> 9;
        centers_s[i] = g_sums[i] / fmaxf(g_counts[b*NC + c], 1.f);
    }
    if (tid < NB){ s_var[tid]=0.f; s_dist[tid]=0.f; s_reg[tid]=0.f; s_np[tid]=0.f; s_npairs[tid]=0.f; }
    __syncthreads();

    for (int i = tid; i < NB*NC; i += 256){
        int b = i >> 5;
        float cnt = g_counts[i];
        if (cnt > 0.f){
            atomicAdd(&s_np[b], 1.f);
            atomicAdd(&s_var[b], g_var[i] / cnt);
            float ss = 0.f;
            #pragma unroll
            for (int e = 0; e < NE; e++){
                float x = centers_s[i*NE + e];
                ss += x * x;
            }
            atomicAdd(&s_reg[b], sqrtf(ss));
        }
    }
    for (int p = tid; p < NB*496; p += 256){
        int b = p / 496, pr = p % 496;
        int i0 = 0, rem = pr;
        while (rem >= (NC - 1 - i0)){ rem -= (NC - 1 - i0); i0++; }
        int j0 = i0 + 1 + rem;
        if (g_counts[b*NC + i0] > 0.f && g_counts[b*NC + j0] > 0.f){
            float ss = 0.f;
            #pragma unroll
            for (int e = 0; e < NE; e++){
                float dd = centers_s[(b*NC + i0)*NE + e] - centers_s[(b*NC + j0)*NE + e];
                ss += dd * dd;
            }
            float ph = fmaxf(3.0f - sqrtf(ss), 0.f);   // 2*DELTA_DIST
            ph *= ph;
            atomicAdd(&s_dist[b], ph);
            atomicAdd(&s_npairs[b], 1.f);
        }
    }
    __syncthreads();

    if (tid == 0){
        float lv = 0.f, ld = 0.f, lr = 0.f, vb = 0.f;
        for (int b = 0; b < NB; b++){
            float np = s_np[b];
            if (np > 0.f){
                vb += 1.f;
                lv += s_var[b] / np;
                lr += s_reg[b] / np;
                ld += (s_npairs[b] > 0.f) ? (s_dist[b] / s_npairs[b]) : 0.f;
            }
        }
        float denom  = fmaxf(vb, 1.f);
        float L_var  = (vb > 0.f) ? lv / denom : 0.f;
        float L_dist = (vb > 0.f) ? ld / denom : 0.f;
        float L_reg  = (vb > 0.f) ? lr / denom : 0.f;
        float total  = 1.0f * L_var + 1.0f * L_dist + 0.001f * L_reg;
        out[0] = total;
        out[1] = L_var;
        out[2] = L_dist;
        out[3] = L_reg;
    }
}

extern "C" void kernel_launch(void* const* d_in, const int* in_sizes, int n_in,
                              void* d_out, int out_size){
    (void)in_sizes; (void)n_in; (void)out_size;
    const float* emb  = (const float*)d_in[0];
    const int*   mask = (const int*)d_in[1];
    k_zero   <<<17, 256>>>();
    k_sums   <<<NB*BPB, 128>>>(emb, mask);
    k_centers<<<16, 256>>>();
    k_var    <<<NB*VBPB, VBL>>>(emb, mask);
    k_final  <<<1, 256>>>((float*)d_out);
}